// round 7
// baseline (speedup 1.0000x reference)
#include <cuda_runtime.h>
#include <cuda_bf16.h>
#include <cstdint>
#include <math.h>

#define BATCH 512
#define SEQ 256
#define EMBED 384
#define HEAD 64

// Scratch for projected Q, K, V
__device__ float g_Q[BATCH * SEQ * HEAD];
__device__ float g_K[BATCH * SEQ * HEAD];
__device__ float g_V[BATCH * SEQ * HEAD];

// ---------------------------------------------------------------------------
// tf32 helpers
// ---------------------------------------------------------------------------
__device__ __forceinline__ float f2tf_f(float x) {
    unsigned r;
    asm("cvt.rna.tf32.f32 %0, %1;" : "=r"(r) : "f"(x));
    return __uint_as_float(r);
}

__device__ __forceinline__ void mma_tf32(float* d, const unsigned* a,
                                         unsigned b0, unsigned b1) {
    asm volatile(
        "mma.sync.aligned.m16n8k8.row.col.f32.tf32.tf32.f32 "
        "{%0,%1,%2,%3}, {%4,%5,%6,%7}, {%8,%9}, {%0,%1,%2,%3};\n"
        : "+f"(d[0]), "+f"(d[1]), "+f"(d[2]), "+f"(d[3])
        : "r"(a[0]), "r"(a[1]), "r"(a[2]), "r"(a[3]), "r"(b0), "r"(b1));
}

// ---------------------------------------------------------------------------
// Kernel 1: fused projection GEMM, software-pipelined, 512 threads.
// (unchanged from the ~196us R6 version)
// ---------------------------------------------------------------------------
#define XPAD 36
#define WPAD 200
#define XS_FLOATS (128 * XPAD)
#define WS_FLOATS (32 * WPAD)
#define PROJ_SMEM ((2 * XS_FLOATS + 2 * WS_FLOATS) * 4)

__global__ __launch_bounds__(512, 1)
void proj_kernel(const float* __restrict__ X,
                 const float* __restrict__ Wk,
                 const float* __restrict__ Wq,
                 const float* __restrict__ Wv)
{
    extern __shared__ float sm[];
    float* Xs[2] = {sm, sm + XS_FLOATS};
    float* Ws[2] = {sm + 2 * XS_FLOATS, sm + 2 * XS_FLOATS + WS_FLOATS};

    const int tid  = threadIdx.x;
    const int lane = tid & 31;
    const int warp = tid >> 5;
    const int g = lane >> 2;
    const int t = lane & 3;
    const int wm = warp & 3;
    const int wn = warp >> 2;
    const int r0 = blockIdx.x * 128;

    const int xrow0 = tid >> 3;
    const int xc4   = (tid & 7) * 4;
    int wrow[3], wc[3];
    const float* wsrc[3];
#pragma unroll
    for (int j = 0; j < 3; j++) {
        int idx = tid + j * 512;
        wrow[j] = idx / 48;
        int c = (idx % 48) * 4;
        wc[j] = c;
        if (c < 64)       wsrc[j] = Wk + c;
        else if (c < 128) wsrc[j] = Wq + (c - 64);
        else              wsrc[j] = Wv + (c - 128);
    }

    float acc[12][4];
#pragma unroll
    for (int f = 0; f < 12; f++)
#pragma unroll
        for (int j = 0; j < 4; j++) acc[f][j] = 0.f;

    float4 xr[2], wr[3];

#pragma unroll
    for (int j = 0; j < 2; j++)
        xr[j] = *(const float4*)(X + (size_t)(r0 + xrow0 + j * 64) * EMBED + xc4);
#pragma unroll
    for (int j = 0; j < 3; j++)
        wr[j] = *(const float4*)(wsrc[j] + (size_t)wrow[j] * HEAD);
#pragma unroll
    for (int j = 0; j < 2; j++) {
        float4 v = xr[j];
        v.x = f2tf_f(v.x); v.y = f2tf_f(v.y);
        v.z = f2tf_f(v.z); v.w = f2tf_f(v.w);
        *(float4*)&Xs[0][(xrow0 + j * 64) * XPAD + xc4] = v;
    }
#pragma unroll
    for (int j = 0; j < 3; j++) {
        float4 v = wr[j];
        v.x = f2tf_f(v.x); v.y = f2tf_f(v.y);
        v.z = f2tf_f(v.z); v.w = f2tf_f(v.w);
        *(float4*)&Ws[0][wrow[j] * WPAD + wc[j]] = v;
    }
    __syncthreads();

#pragma unroll 1
    for (int c = 0; c < 12; c++) {
        const int cb = c & 1;
        if (c < 11) {
            const int kk = (c + 1) * 32;
#pragma unroll
            for (int j = 0; j < 2; j++)
                xr[j] = *(const float4*)(X + (size_t)(r0 + xrow0 + j * 64) * EMBED + kk + xc4);
#pragma unroll
            for (int j = 0; j < 3; j++)
                wr[j] = *(const float4*)(wsrc[j] + (size_t)(kk + wrow[j]) * HEAD);
        }

        const float* Xb = Xs[cb];
        const float* Wb = Ws[cb];
#pragma unroll
        for (int ks = 0; ks < 4; ks++) {
            const int kb = ks * 8;
            unsigned a0[4], a1[4];
            const int rA = wm * 32 + g;
            a0[0] = __float_as_uint(Xb[rA * XPAD + kb + t]);
            a0[1] = __float_as_uint(Xb[(rA + 8) * XPAD + kb + t]);
            a0[2] = __float_as_uint(Xb[rA * XPAD + kb + t + 4]);
            a0[3] = __float_as_uint(Xb[(rA + 8) * XPAD + kb + t + 4]);
            a1[0] = __float_as_uint(Xb[(rA + 16) * XPAD + kb + t]);
            a1[1] = __float_as_uint(Xb[(rA + 24) * XPAD + kb + t]);
            a1[2] = __float_as_uint(Xb[(rA + 16) * XPAD + kb + t + 4]);
            a1[3] = __float_as_uint(Xb[(rA + 24) * XPAD + kb + t + 4]);
#pragma unroll
            for (int f = 0; f < 6; f++) {
                int col = wn * 48 + f * 8 + g;
                unsigned b0 = __float_as_uint(Wb[(kb + t) * WPAD + col]);
                unsigned b1 = __float_as_uint(Wb[(kb + t + 4) * WPAD + col]);
                mma_tf32(acc[f], a0, b0, b1);
                mma_tf32(acc[6 + f], a1, b0, b1);
            }
        }

        if (c < 11) {
            const int nb = 1 - cb;
#pragma unroll
            for (int j = 0; j < 2; j++) {
                float4 v = xr[j];
                v.x = f2tf_f(v.x); v.y = f2tf_f(v.y);
                v.z = f2tf_f(v.z); v.w = f2tf_f(v.w);
                *(float4*)&Xs[nb][(xrow0 + j * 64) * XPAD + xc4] = v;
            }
#pragma unroll
            for (int j = 0; j < 3; j++) {
                float4 v = wr[j];
                v.x = f2tf_f(v.x); v.y = f2tf_f(v.y);
                v.z = f2tf_f(v.z); v.w = f2tf_f(v.w);
                *(float4*)&Ws[nb][wrow[j] * WPAD + wc[j]] = v;
            }
        }
        __syncthreads();
    }

#pragma unroll
    for (int mf = 0; mf < 2; mf++) {
#pragma unroll
        for (int f = 0; f < 6; f++) {
            const float* a = acc[mf * 6 + f];
            int n = wn * 48 + f * 8 + 2 * t;
            float* dst;
            int nn;
            if (n < 64)       { dst = g_K; nn = n; }
            else if (n < 128) { dst = g_Q; nn = n - 64; }
            else              { dst = g_V; nn = n - 128; }
            size_t row = (size_t)(r0 + wm * 32 + mf * 16 + g);
            *(float2*)&dst[row * HEAD + nn]       = make_float2(a[0], a[1]);
            *(float2*)&dst[(row + 8) * HEAD + nn] = make_float2(a[2], a[3]);
        }
    }
}

// ---------------------------------------------------------------------------
// Kernel 2: causal attention, tf32 mma.sync, flash online softmax.
// NEW: 512 threads = 16 warps; warp w owns q-tile w (single pass).
// P buffer aliases the (dead after frag extraction) Q buffer -> smem fits.
// ---------------------------------------------------------------------------
#define KVPAD 68
#define QPAD  68
#define ATTN_SMEM ((2 * SEQ * KVPAD + 16 * 16 * QPAD) * (int)sizeof(float))

__global__ __launch_bounds__(512, 1)
void attn_kernel(float* __restrict__ out)
{
    extern __shared__ float smf[];
    float* Ks = smf;                       // [256][68]
    float* Vs = Ks + SEQ * KVPAD;          // [256][68]
    float* QP = Vs + SEQ * KVPAD;          // [16][16][68]  Q then P

    const int b    = blockIdx.x;
    const int tid  = threadIdx.x;
    const int lane = tid & 31;
    const int warp = tid >> 5;             // 0..15 = q-tile
    const int g = lane >> 2;
    const int t = lane & 3;
    const size_t base = (size_t)b * SEQ * HEAD;

    // Stage K, V (tf32-rounded), 512 threads coalesced float4
    for (int i = tid; i < SEQ * HEAD / 4; i += 512) {
        int s = i >> 4;
        int d = (i & 15) * 4;
        float4 k4 = *(const float4*)&g_K[base + (size_t)s * HEAD + d];
        float4 v4 = *(const float4*)&g_V[base + (size_t)s * HEAD + d];
        k4.x = f2tf_f(k4.x); k4.y = f2tf_f(k4.y);
        k4.z = f2tf_f(k4.z); k4.w = f2tf_f(k4.w);
        v4.x = f2tf_f(v4.x); v4.y = f2tf_f(v4.y);
        v4.z = f2tf_f(v4.z); v4.w = f2tf_f(v4.w);
        *(float4*)&Ks[s * KVPAD + d] = k4;
        *(float4*)&Vs[s * KVPAD + d] = v4;
    }
    __syncthreads();

    float* Qw = QP + warp * 16 * QPAD;     // 16 x 64 (pad 68)
    const int qr0 = warp * 16;

    // Stage this warp's Q tile, tf32-converted
#pragma unroll
    for (int i = 0; i < 8; i++) {
        int idx = lane + i * 32;
        int row = idx >> 4;
        int c4  = (idx & 15) * 4;
        float4 q4 = *(const float4*)&g_Q[base + (size_t)(qr0 + row) * HEAD + c4];
        q4.x = f2tf_f(q4.x); q4.y = f2tf_f(q4.y);
        q4.z = f2tf_f(q4.z); q4.w = f2tf_f(q4.w);
        *(float4*)&Qw[row * QPAD + c4] = q4;
    }
    __syncwarp();

    // Extract Q fragments once; afterwards Qw is dead and reused as P.
    unsigned qf[8][4];
#pragma unroll
    for (int ks = 0; ks < 8; ks++) {
        int kb = ks * 8;
        qf[ks][0] = __float_as_uint(Qw[g * QPAD + kb + t]);
        qf[ks][1] = __float_as_uint(Qw[(g + 8) * QPAD + kb + t]);
        qf[ks][2] = __float_as_uint(Qw[g * QPAD + kb + t + 4]);
        qf[ks][3] = __float_as_uint(Qw[(g + 8) * QPAD + kb + t + 4]);
    }
    __syncwarp();
    float* Pw = Qw;    // alias

    float of[8][4];
#pragma unroll
    for (int f = 0; f < 8; f++)
#pragma unroll
        for (int j = 0; j < 4; j++) of[f][j] = 0.f;

    float m0 = -1e30f, m1 = -1e30f, l0 = 0.f, l1 = 0.f;
    const int rg  = qr0 + g;
    const int rg8 = rg + 8;
    const int jmax = (qr0 + 15) >> 5;

    for (int j = 0; j <= jmax; j++) {
        // ---- S = Q @ K^T for kv chunk [32j, 32j+31] ----
        float s[4][4];
#pragma unroll
        for (int nf = 0; nf < 4; nf++)
#pragma unroll
            for (int e = 0; e < 4; e++) s[nf][e] = 0.f;

#pragma unroll
        for (int ks = 0; ks < 8; ks++) {
            int kb = ks * 8;
#pragma unroll
            for (int nf = 0; nf < 4; nf++) {
                int col = j * 32 + nf * 8 + g;
                unsigned b0 = __float_as_uint(Ks[col * KVPAD + kb + t]);
                unsigned b1 = __float_as_uint(Ks[col * KVPAD + kb + t + 4]);
                mma_tf32(s[nf], qf[ks], b0, b1);
            }
        }

        // scale + causal mask (only last chunk crosses the diagonal)
#pragma unroll
        for (int nf = 0; nf < 4; nf++) {
            int c0 = j * 32 + nf * 8 + 2 * t;
            s[nf][0] *= 0.125f; s[nf][1] *= 0.125f;
            s[nf][2] *= 0.125f; s[nf][3] *= 0.125f;
            if (j == jmax) {
                if (c0 > rg)      s[nf][0] = -1e30f;
                if (c0 + 1 > rg)  s[nf][1] = -1e30f;
                if (c0 > rg8)     s[nf][2] = -1e30f;
                if (c0 + 1 > rg8) s[nf][3] = -1e30f;
            }
        }

        // ---- online softmax (rows g and g+8) ----
        float nm0 = m0, nm1 = m1;
#pragma unroll
        for (int nf = 0; nf < 4; nf++) {
            nm0 = fmaxf(nm0, fmaxf(s[nf][0], s[nf][1]));
            nm1 = fmaxf(nm1, fmaxf(s[nf][2], s[nf][3]));
        }
        nm0 = fmaxf(nm0, __shfl_xor_sync(0xFFFFFFFFu, nm0, 1));
        nm0 = fmaxf(nm0, __shfl_xor_sync(0xFFFFFFFFu, nm0, 2));
        nm1 = fmaxf(nm1, __shfl_xor_sync(0xFFFFFFFFu, nm1, 1));
        nm1 = fmaxf(nm1, __shfl_xor_sync(0xFFFFFFFFu, nm1, 2));

        float al0 = __expf(m0 - nm0);
        float al1 = __expf(m1 - nm1);

        float ps0 = 0.f, ps1 = 0.f;
#pragma unroll
        for (int nf = 0; nf < 4; nf++) {
            float p0 = __expf(s[nf][0] - nm0);
            float p1 = __expf(s[nf][1] - nm0);
            float p2 = __expf(s[nf][2] - nm1);
            float p3 = __expf(s[nf][3] - nm1);
            ps0 += p0 + p1;
            ps1 += p2 + p3;
            int cl = nf * 8 + 2 * t;
            *(float2*)&Pw[g * QPAD + cl] =
                make_float2(f2tf_f(p0), f2tf_f(p1));
            *(float2*)&Pw[(g + 8) * QPAD + cl] =
                make_float2(f2tf_f(p2), f2tf_f(p3));
        }
        ps0 += __shfl_xor_sync(0xFFFFFFFFu, ps0, 1);
        ps0 += __shfl_xor_sync(0xFFFFFFFFu, ps0, 2);
        ps1 += __shfl_xor_sync(0xFFFFFFFFu, ps1, 1);
        ps1 += __shfl_xor_sync(0xFFFFFFFFu, ps1, 2);

        l0 = l0 * al0 + ps0;
        l1 = l1 * al1 + ps1;
        m0 = nm0; m1 = nm1;

#pragma unroll
        for (int f = 0; f < 8; f++) {
            of[f][0] *= al0; of[f][1] *= al0;
            of[f][2] *= al1; of[f][3] *= al1;
        }
        __syncwarp();   // P writes visible to whole warp

        // ---- O += P @ V ----
#pragma unroll
        for (int ks = 0; ks < 4; ks++) {
            int kb = ks * 8;
            unsigned pa[4];
            pa[0] = __float_as_uint(Pw[g * QPAD + kb + t]);
            pa[1] = __float_as_uint(Pw[(g + 8) * QPAD + kb + t]);
            pa[2] = __float_as_uint(Pw[g * QPAD + kb + t + 4]);
            pa[3] = __float_as_uint(Pw[(g + 8) * QPAD + kb + t + 4]);
            int vr = j * 32 + kb;
#pragma unroll
            for (int nf = 0; nf < 8; nf++) {
                int col = nf * 8 + g;
                unsigned b0 = __float_as_uint(Vs[(vr + t) * KVPAD + col]);
                unsigned b1 = __float_as_uint(Vs[(vr + t + 4) * KVPAD + col]);
                mma_tf32(of[nf], pa, b0, b1);
            }
        }
        __syncwarp();   // done reading P before next chunk overwrites
    }

    // Epilogue
    float inv0 = 1.f / l0;
    float inv1 = 1.f / l1;
#pragma unroll
    for (int nf = 0; nf < 8; nf++) {
        int col = nf * 8 + 2 * t;
        size_t row = (size_t)(qr0 + g);
        *(float2*)&out[base + row * HEAD + col] =
            make_float2(of[nf][0] * inv0, of[nf][1] * inv0);
        *(float2*)&out[base + (row + 8) * HEAD + col] =
            make_float2(of[nf][2] * inv1, of[nf][3] * inv1);
    }
}

// ---------------------------------------------------------------------------
extern "C" void kernel_launch(void* const* d_in, const int* in_sizes, int n_in,
                              void* d_out, int out_size)
{
    const float* X  = (const float*)d_in[0];
    const float* Wk = (const float*)d_in[1];
    const float* Wq = (const float*)d_in[2];
    const float* Wv = (const float*)d_in[3];
    float* out = (float*)d_out;

    static bool attr_set = false;
    if (!attr_set) {
        cudaFuncSetAttribute(proj_kernel,
                             cudaFuncAttributeMaxDynamicSharedMemorySize,
                             PROJ_SMEM);
        cudaFuncSetAttribute(attn_kernel,
                             cudaFuncAttributeMaxDynamicSharedMemorySize,
                             ATTN_SMEM);
        attr_set = true;
    }

    proj_kernel<<<(BATCH * SEQ) / 128, 512, PROJ_SMEM>>>(X, Wk, Wq, Wv);
    attn_kernel<<<BATCH, 512, ATTN_SMEM>>>(out);
}

// round 8
// speedup vs baseline: 1.2609x; 1.2609x over previous
#include <cuda_runtime.h>
#include <cuda_bf16.h>
#include <cstdint>
#include <math.h>

#define BATCH 512
#define SEQ 256
#define EMBED 384
#define HEAD 64

// Scratch for projected Q, K, V
__device__ float g_Q[BATCH * SEQ * HEAD];
__device__ float g_K[BATCH * SEQ * HEAD];
__device__ float g_V[BATCH * SEQ * HEAD];

// ---------------------------------------------------------------------------
// tf32 helpers
// ---------------------------------------------------------------------------
__device__ __forceinline__ float f2tf_f(float x) {
    unsigned r;
    asm("cvt.rna.tf32.f32 %0, %1;" : "=r"(r) : "f"(x));
    return __uint_as_float(r);
}

__device__ __forceinline__ void mma_tf32(float* d, const unsigned* a,
                                         unsigned b0, unsigned b1) {
    asm volatile(
        "mma.sync.aligned.m16n8k8.row.col.f32.tf32.tf32.f32 "
        "{%0,%1,%2,%3}, {%4,%5,%6,%7}, {%8,%9}, {%0,%1,%2,%3};\n"
        : "+f"(d[0]), "+f"(d[1]), "+f"(d[2]), "+f"(d[3])
        : "r"(a[0]), "r"(a[1]), "r"(a[2]), "r"(a[3]), "r"(b0), "r"(b1));
}

// ---------------------------------------------------------------------------
// Kernel 1: fused projection GEMM, software-pipelined, 1024 threads.
// C[131072 x 192] = X[131072 x 384] @ [Wk|Wq|Wv]
// CTA tile M=128, N=192; k-chunks of 32, double-buffered smem.
// Warp grid 4(m) x 8(n); warp tile 32 x 24 = 2 m-frags x 3 n-frags.
// ---------------------------------------------------------------------------
#define XPAD 36    // A-frag loads hit banks 4g+t -> conflict-free
#define WPAD 200   // B-frag loads hit banks 8t+g (+8*wn) -> conflict-free
#define XS_FLOATS (128 * XPAD)
#define WS_FLOATS (32 * WPAD)
#define PROJ_SMEM ((2 * XS_FLOATS + 2 * WS_FLOATS) * 4)   // 88064 B

__global__ __launch_bounds__(1024, 1)
void proj_kernel(const float* __restrict__ X,
                 const float* __restrict__ Wk,
                 const float* __restrict__ Wq,
                 const float* __restrict__ Wv)
{
    extern __shared__ float sm[];
    float* Xs[2] = {sm, sm + XS_FLOATS};
    float* Ws[2] = {sm + 2 * XS_FLOATS, sm + 2 * XS_FLOATS + WS_FLOATS};

    const int tid  = threadIdx.x;
    const int lane = tid & 31;
    const int warp = tid >> 5;
    const int g = lane >> 2;   // 0..7
    const int t = lane & 3;    // 0..3
    const int wm = warp & 3;   // m-warp: rows wm*32 .. +31
    const int wn = warp >> 2;  // n-warp: cols wn*24 .. +23
    const int r0 = blockIdx.x * 128;

    // staging indices: X tile 128x32 = 1024 float4 -> 1 per thread
    const int xrow = tid >> 3;
    const int xc4  = (tid & 7) * 4;
    // W tile 32x192 = 1536 float4 -> thread handles idx {tid, tid+1024<1536}
    int wrow[2], wc[2];
    const float* wsrc[2];
    bool wact[2];
#pragma unroll
    for (int j = 0; j < 2; j++) {
        int idx = tid + j * 1024;
        wact[j] = (idx < 1536);
        int ii = wact[j] ? idx : 0;
        wrow[j] = ii / 48;
        int c = (ii % 48) * 4;
        wc[j] = c;
        if (c < 64)       wsrc[j] = Wk + c;
        else if (c < 128) wsrc[j] = Wq + (c - 64);
        else              wsrc[j] = Wv + (c - 128);
    }

    float acc[6][4];
#pragma unroll
    for (int f = 0; f < 6; f++)
#pragma unroll
        for (int j = 0; j < 4; j++) acc[f][j] = 0.f;

    float4 xr, wr[2];

    // ---- prologue: load + store chunk 0 ----
    xr = *(const float4*)(X + (size_t)(r0 + xrow) * EMBED + xc4);
#pragma unroll
    for (int j = 0; j < 2; j++)
        if (wact[j]) wr[j] = *(const float4*)(wsrc[j] + (size_t)wrow[j] * HEAD);
    {
        float4 v = xr;
        v.x = f2tf_f(v.x); v.y = f2tf_f(v.y);
        v.z = f2tf_f(v.z); v.w = f2tf_f(v.w);
        *(float4*)&Xs[0][xrow * XPAD + xc4] = v;
    }
#pragma unroll
    for (int j = 0; j < 2; j++)
        if (wact[j]) {
            float4 v = wr[j];
            v.x = f2tf_f(v.x); v.y = f2tf_f(v.y);
            v.z = f2tf_f(v.z); v.w = f2tf_f(v.w);
            *(float4*)&Ws[0][wrow[j] * WPAD + wc[j]] = v;
        }
    __syncthreads();

#pragma unroll 1
    for (int c = 0; c < 12; c++) {
        const int cb = c & 1;
        // issue global loads for next chunk
        if (c < 11) {
            const int kk = (c + 1) * 32;
            xr = *(const float4*)(X + (size_t)(r0 + xrow) * EMBED + kk + xc4);
#pragma unroll
            for (int j = 0; j < 2; j++)
                if (wact[j])
                    wr[j] = *(const float4*)(wsrc[j] + (size_t)(kk + wrow[j]) * HEAD);
        }

        // compute on current buffer
        const float* Xb = Xs[cb];
        const float* Wb = Ws[cb];
#pragma unroll
        for (int ks = 0; ks < 4; ks++) {
            const int kb = ks * 8;
            unsigned a0[4], a1[4];
            const int rA = wm * 32 + g;
            a0[0] = __float_as_uint(Xb[rA * XPAD + kb + t]);
            a0[1] = __float_as_uint(Xb[(rA + 8) * XPAD + kb + t]);
            a0[2] = __float_as_uint(Xb[rA * XPAD + kb + t + 4]);
            a0[3] = __float_as_uint(Xb[(rA + 8) * XPAD + kb + t + 4]);
            a1[0] = __float_as_uint(Xb[(rA + 16) * XPAD + kb + t]);
            a1[1] = __float_as_uint(Xb[(rA + 24) * XPAD + kb + t]);
            a1[2] = __float_as_uint(Xb[(rA + 16) * XPAD + kb + t + 4]);
            a1[3] = __float_as_uint(Xb[(rA + 24) * XPAD + kb + t + 4]);
#pragma unroll
            for (int f = 0; f < 3; f++) {
                int col = wn * 24 + f * 8 + g;
                unsigned b0 = __float_as_uint(Wb[(kb + t) * WPAD + col]);
                unsigned b1 = __float_as_uint(Wb[(kb + t + 4) * WPAD + col]);
                mma_tf32(acc[f], a0, b0, b1);
                mma_tf32(acc[3 + f], a1, b0, b1);
            }
        }

        // store next chunk into the idle buffer
        if (c < 11) {
            const int nb = 1 - cb;
            {
                float4 v = xr;
                v.x = f2tf_f(v.x); v.y = f2tf_f(v.y);
                v.z = f2tf_f(v.z); v.w = f2tf_f(v.w);
                *(float4*)&Xs[nb][xrow * XPAD + xc4] = v;
            }
#pragma unroll
            for (int j = 0; j < 2; j++)
                if (wact[j]) {
                    float4 v = wr[j];
                    v.x = f2tf_f(v.x); v.y = f2tf_f(v.y);
                    v.z = f2tf_f(v.z); v.w = f2tf_f(v.w);
                    *(float4*)&Ws[nb][wrow[j] * WPAD + wc[j]] = v;
                }
        }
        __syncthreads();
    }

    // ---- epilogue: route columns to K / Q / V ----
#pragma unroll
    for (int mf = 0; mf < 2; mf++) {
#pragma unroll
        for (int f = 0; f < 3; f++) {
            const float* a = acc[mf * 3 + f];
            int n = wn * 24 + f * 8 + 2 * t;
            float* dst;
            int nn;
            if (n < 64)       { dst = g_K; nn = n; }
            else if (n < 128) { dst = g_Q; nn = n - 64; }
            else              { dst = g_V; nn = n - 128; }
            size_t row = (size_t)(r0 + wm * 32 + mf * 16 + g);
            *(float2*)&dst[row * HEAD + nn]       = make_float2(a[0], a[1]);
            *(float2*)&dst[(row + 8) * HEAD + nn] = make_float2(a[2], a[3]);
        }
    }
}

// ---------------------------------------------------------------------------
// Kernel 2: causal attention, tf32 mma.sync, flash online softmax.
// (exact revert to the known-good 94.9us R6 version: 256 thr, paired tiles)
// ---------------------------------------------------------------------------
#define KVPAD 68
#define QPAD  68
#define PPAD  36

__global__ __launch_bounds__(256, 1)
void attn_kernel(float* __restrict__ out)
{
    extern __shared__ float smf[];
    float* Ks = smf;
    float* Vs = Ks + SEQ * KVPAD;
    float* Qs = Vs + SEQ * KVPAD;
    float* Pb = Qs + 8 * 16 * QPAD;

    const int b    = blockIdx.x;
    const int tid  = threadIdx.x;
    const int lane = tid & 31;
    const int warp = tid >> 5;
    const int g = lane >> 2;
    const int t = lane & 3;
    const size_t base = (size_t)b * SEQ * HEAD;

    for (int i = tid; i < SEQ * HEAD / 4; i += 256) {
        int s = i >> 4;
        int d = (i & 15) * 4;
        float4 k4 = *(const float4*)&g_K[base + (size_t)s * HEAD + d];
        float4 v4 = *(const float4*)&g_V[base + (size_t)s * HEAD + d];
        k4.x = f2tf_f(k4.x); k4.y = f2tf_f(k4.y);
        k4.z = f2tf_f(k4.z); k4.w = f2tf_f(k4.w);
        v4.x = f2tf_f(v4.x); v4.y = f2tf_f(v4.y);
        v4.z = f2tf_f(v4.z); v4.w = f2tf_f(v4.w);
        *(float4*)&Ks[s * KVPAD + d] = k4;
        *(float4*)&Vs[s * KVPAD + d] = v4;
    }
    __syncthreads();

    float* Qw = Qs + warp * 16 * QPAD;
    float* Pw = Pb + warp * 16 * PPAD;

#pragma unroll
    for (int pass = 0; pass < 2; pass++) {
        const int qt = pass ? (15 - warp) : warp;
        const int qr0 = qt * 16;

#pragma unroll
        for (int i = 0; i < 8; i++) {
            int idx = lane + i * 32;
            int row = idx >> 4;
            int c4  = (idx & 15) * 4;
            float4 q4 = *(const float4*)&g_Q[base + (size_t)(qr0 + row) * HEAD + c4];
            q4.x = f2tf_f(q4.x); q4.y = f2tf_f(q4.y);
            q4.z = f2tf_f(q4.z); q4.w = f2tf_f(q4.w);
            *(float4*)&Qw[row * QPAD + c4] = q4;
        }
        __syncwarp();

        unsigned qf[8][4];
#pragma unroll
        for (int ks = 0; ks < 8; ks++) {
            int kb = ks * 8;
            qf[ks][0] = __float_as_uint(Qw[g * QPAD + kb + t]);
            qf[ks][1] = __float_as_uint(Qw[(g + 8) * QPAD + kb + t]);
            qf[ks][2] = __float_as_uint(Qw[g * QPAD + kb + t + 4]);
            qf[ks][3] = __float_as_uint(Qw[(g + 8) * QPAD + kb + t + 4]);
        }

        float of[8][4];
#pragma unroll
        for (int f = 0; f < 8; f++)
#pragma unroll
            for (int j = 0; j < 4; j++) of[f][j] = 0.f;

        float m0 = -1e30f, m1 = -1e30f, l0 = 0.f, l1 = 0.f;
        const int rg  = qr0 + g;
        const int rg8 = rg + 8;
        const int jmax = (qr0 + 15) >> 5;

        for (int j = 0; j <= jmax; j++) {
            float s[4][4];
#pragma unroll
            for (int nf = 0; nf < 4; nf++)
#pragma unroll
                for (int e = 0; e < 4; e++) s[nf][e] = 0.f;

#pragma unroll
            for (int ks = 0; ks < 8; ks++) {
                int kb = ks * 8;
#pragma unroll
                for (int nf = 0; nf < 4; nf++) {
                    int col = j * 32 + nf * 8 + g;
                    unsigned b0 = __float_as_uint(Ks[col * KVPAD + kb + t]);
                    unsigned b1 = __float_as_uint(Ks[col * KVPAD + kb + t + 4]);
                    mma_tf32(s[nf], qf[ks], b0, b1);
                }
            }

#pragma unroll
            for (int nf = 0; nf < 4; nf++) {
                int c0 = j * 32 + nf * 8 + 2 * t;
                s[nf][0] *= 0.125f; s[nf][1] *= 0.125f;
                s[nf][2] *= 0.125f; s[nf][3] *= 0.125f;
                if (j == jmax) {
                    if (c0 > rg)      s[nf][0] = -1e30f;
                    if (c0 + 1 > rg)  s[nf][1] = -1e30f;
                    if (c0 > rg8)     s[nf][2] = -1e30f;
                    if (c0 + 1 > rg8) s[nf][3] = -1e30f;
                }
            }

            float nm0 = m0, nm1 = m1;
#pragma unroll
            for (int nf = 0; nf < 4; nf++) {
                nm0 = fmaxf(nm0, fmaxf(s[nf][0], s[nf][1]));
                nm1 = fmaxf(nm1, fmaxf(s[nf][2], s[nf][3]));
            }
            nm0 = fmaxf(nm0, __shfl_xor_sync(0xFFFFFFFFu, nm0, 1));
            nm0 = fmaxf(nm0, __shfl_xor_sync(0xFFFFFFFFu, nm0, 2));
            nm1 = fmaxf(nm1, __shfl_xor_sync(0xFFFFFFFFu, nm1, 1));
            nm1 = fmaxf(nm1, __shfl_xor_sync(0xFFFFFFFFu, nm1, 2));

            float al0 = __expf(m0 - nm0);
            float al1 = __expf(m1 - nm1);

            float ps0 = 0.f, ps1 = 0.f;
#pragma unroll
            for (int nf = 0; nf < 4; nf++) {
                float p0 = __expf(s[nf][0] - nm0);
                float p1 = __expf(s[nf][1] - nm0);
                float p2 = __expf(s[nf][2] - nm1);
                float p3 = __expf(s[nf][3] - nm1);
                ps0 += p0 + p1;
                ps1 += p2 + p3;
                int cl = nf * 8 + 2 * t;
                *(float2*)&Pw[g * PPAD + cl] =
                    make_float2(f2tf_f(p0), f2tf_f(p1));
                *(float2*)&Pw[(g + 8) * PPAD + cl] =
                    make_float2(f2tf_f(p2), f2tf_f(p3));
            }
            ps0 += __shfl_xor_sync(0xFFFFFFFFu, ps0, 1);
            ps0 += __shfl_xor_sync(0xFFFFFFFFu, ps0, 2);
            ps1 += __shfl_xor_sync(0xFFFFFFFFu, ps1, 1);
            ps1 += __shfl_xor_sync(0xFFFFFFFFu, ps1, 2);

            l0 = l0 * al0 + ps0;
            l1 = l1 * al1 + ps1;
            m0 = nm0; m1 = nm1;

#pragma unroll
            for (int f = 0; f < 8; f++) {
                of[f][0] *= al0; of[f][1] *= al0;
                of[f][2] *= al1; of[f][3] *= al1;
            }
            __syncwarp();

#pragma unroll
            for (int ks = 0; ks < 4; ks++) {
                int kb = ks * 8;
                unsigned pa[4];
                pa[0] = __float_as_uint(Pw[g * PPAD + kb + t]);
                pa[1] = __float_as_uint(Pw[(g + 8) * PPAD + kb + t]);
                pa[2] = __float_as_uint(Pw[g * PPAD + kb + t + 4]);
                pa[3] = __float_as_uint(Pw[(g + 8) * PPAD + kb + t + 4]);
                int vr = j * 32 + kb;
#pragma unroll
                for (int nf = 0; nf < 8; nf++) {
                    int col = nf * 8 + g;
                    unsigned b0 = __float_as_uint(Vs[(vr + t) * KVPAD + col]);
                    unsigned b1 = __float_as_uint(Vs[(vr + t + 4) * KVPAD + col]);
                    mma_tf32(of[nf], pa, b0, b1);
                }
            }
            __syncwarp();
        }

        float inv0 = 1.f / l0;
        float inv1 = 1.f / l1;
#pragma unroll
        for (int nf = 0; nf < 8; nf++) {
            int col = nf * 8 + 2 * t;
            size_t row = (size_t)(qr0 + g);
            *(float2*)&out[base + row * HEAD + col] =
                make_float2(of[nf][0] * inv0, of[nf][1] * inv0);
            *(float2*)&out[base + (row + 8) * HEAD + col] =
                make_float2(of[nf][2] * inv1, of[nf][3] * inv1);
        }
    }
}

// ---------------------------------------------------------------------------
extern "C" void kernel_launch(void* const* d_in, const int* in_sizes, int n_in,
                              void* d_out, int out_size)
{
    const float* X  = (const float*)d_in[0];
    const float* Wk = (const float*)d_in[1];
    const float* Wq = (const float*)d_in[2];
    const float* Wv = (const float*)d_in[3];
    float* out = (float*)d_out;

    const int attn_smem =
        (2 * SEQ * KVPAD + 8 * 16 * QPAD + 8 * 16 * PPAD) * (int)sizeof(float);

    static bool attr_set = false;
    if (!attr_set) {
        cudaFuncSetAttribute(proj_kernel,
                             cudaFuncAttributeMaxDynamicSharedMemorySize,
                             PROJ_SMEM);
        cudaFuncSetAttribute(attn_kernel,
                             cudaFuncAttributeMaxDynamicSharedMemorySize,
                             attn_smem);
        attr_set = true;
    }

    proj_kernel<<<(BATCH * SEQ) / 128, 1024, PROJ_SMEM>>>(X, Wk, Wq, Wv);
    attn_kernel<<<BATCH, 256, attn_smem>>>(out);
}

// round 9
// speedup vs baseline: 1.3804x; 1.0948x over previous
#include <cuda_runtime.h>
#include <cuda_bf16.h>
#include <cstdint>
#include <math.h>

#define BATCH 512
#define SEQ 256
#define EMBED 384
#define HEAD 64

// Scratch for projected Q, K, V
__device__ float g_Q[BATCH * SEQ * HEAD];
__device__ float g_K[BATCH * SEQ * HEAD];
__device__ float g_V[BATCH * SEQ * HEAD];

// ---------------------------------------------------------------------------
// helpers
// ---------------------------------------------------------------------------
__device__ __forceinline__ float f2tf_f(float x) {
    unsigned r;
    asm("cvt.rna.tf32.f32 %0, %1;" : "=r"(r) : "f"(x));
    return __uint_as_float(r);
}
__device__ __forceinline__ unsigned f2tf(float x) {
    unsigned r;
    asm("cvt.rna.tf32.f32 %0, %1;" : "=r"(r) : "f"(x));
    return r;
}

__device__ __forceinline__ void mma_tf32(float* d, const unsigned* a,
                                         unsigned b0, unsigned b1) {
    asm volatile(
        "mma.sync.aligned.m16n8k8.row.col.f32.tf32.tf32.f32 "
        "{%0,%1,%2,%3}, {%4,%5,%6,%7}, {%8,%9}, {%0,%1,%2,%3};\n"
        : "+f"(d[0]), "+f"(d[1]), "+f"(d[2]), "+f"(d[3])
        : "r"(a[0]), "r"(a[1]), "r"(a[2]), "r"(a[3]), "r"(b0), "r"(b1));
}

__device__ __forceinline__ uint32_t smem_u32(const void* p) {
    uint32_t a;
    asm("{ .reg .u64 t; cvta.to.shared.u64 t, %1; cvt.u32.u64 %0, t; }"
        : "=r"(a) : "l"(p));
    return a;
}

__device__ __forceinline__ void cpa16(uint32_t dst, const void* src) {
    asm volatile("cp.async.cg.shared.global [%0], [%1], 16;"
                 :: "r"(dst), "l"(src) : "memory");
}
#define CPA_COMMIT() asm volatile("cp.async.commit_group;" ::: "memory")
#define CPA_WAIT1()  asm volatile("cp.async.wait_group 1;" ::: "memory")

// ---------------------------------------------------------------------------
// Kernel 1: fused projection GEMM, cp.async double-buffered, 512 threads.
// C[131072 x 192] = X[131072 x 384] @ [Wk|Wq|Wv]
// CTA tile M=128, N=192; k-chunks of 32.
// Warp grid 4(m) x 4(n); warp tile 32 x 48 = 2 m-frags x 6 n-frags.
// Fragments cvt.rna'd to tf32 at use (numerically identical to staging-time).
// ---------------------------------------------------------------------------
#define XPAD 36    // A-frag loads hit banks 4g+t -> conflict-free
#define WPAD 200   // B-frag loads hit banks 8t+g -> conflict-free
#define XS_FLOATS (128 * XPAD)
#define WS_FLOATS (32 * WPAD)
#define PROJ_SMEM ((2 * XS_FLOATS + 2 * WS_FLOATS) * 4)   // 88064 B -> 2 CTA/SM

__global__ __launch_bounds__(512, 1)
void proj_kernel(const float* __restrict__ X,
                 const float* __restrict__ Wk,
                 const float* __restrict__ Wq,
                 const float* __restrict__ Wv)
{
    extern __shared__ float sm[];
    float* Xs[2] = {sm, sm + XS_FLOATS};
    float* Ws[2] = {sm + 2 * XS_FLOATS, sm + 2 * XS_FLOATS + WS_FLOATS};

    const int tid  = threadIdx.x;
    const int lane = tid & 31;
    const int warp = tid >> 5;
    const int g = lane >> 2;   // 0..7
    const int t = lane & 3;    // 0..3
    const int wm = warp & 3;   // m-warp: rows wm*32 .. +31
    const int wn = warp >> 2;  // n-warp: cols wn*48 .. +47
    const int r0 = blockIdx.x * 128;

    // ---- staging indices ----
    // X tile 128x32 = 1024 float4: 2 per thread (idx = tid + j*512)
    int xrow[2], xc4[2];
    uint32_t xdst[2][2];
#pragma unroll
    for (int j = 0; j < 2; j++) {
        int idx = tid + j * 512;
        xrow[j] = idx >> 3;
        xc4[j]  = (idx & 7) * 4;
        xdst[0][j] = smem_u32(&Xs[0][xrow[j] * XPAD + xc4[j]]);
        xdst[1][j] = smem_u32(&Xs[1][xrow[j] * XPAD + xc4[j]]);
    }
    // W tile 32x192 = 1536 float4: 3 per thread
    int wrow[3];
    const float* wsrc[3];
    uint32_t wdst[2][3];
#pragma unroll
    for (int j = 0; j < 3; j++) {
        int idx = tid + j * 512;
        wrow[j] = idx / 48;
        int c = (idx % 48) * 4;
        if (c < 64)       wsrc[j] = Wk + c;
        else if (c < 128) wsrc[j] = Wq + (c - 64);
        else              wsrc[j] = Wv + (c - 128);
        wdst[0][j] = smem_u32(&Ws[0][wrow[j] * WPAD + c]);
        wdst[1][j] = smem_u32(&Ws[1][wrow[j] * WPAD + c]);
    }

    float acc[12][4];
#pragma unroll
    for (int f = 0; f < 12; f++)
#pragma unroll
        for (int j = 0; j < 4; j++) acc[f][j] = 0.f;

    // ---- prologue: issue chunk 0 into buffer 0 ----
#pragma unroll
    for (int j = 0; j < 2; j++)
        cpa16(xdst[0][j], X + (size_t)(r0 + xrow[j]) * EMBED + xc4[j]);
#pragma unroll
    for (int j = 0; j < 3; j++)
        cpa16(wdst[0][j], wsrc[j] + (size_t)wrow[j] * HEAD);
    CPA_COMMIT();

#pragma unroll 1
    for (int c = 0; c < 12; c++) {
        const int cb = c & 1;
        // issue next chunk into the other buffer (readers of it synced last iter)
        if (c < 11) {
            const int nb = 1 - cb;
            const int kk = (c + 1) * 32;
#pragma unroll
            for (int j = 0; j < 2; j++)
                cpa16(xdst[nb][j], X + (size_t)(r0 + xrow[j]) * EMBED + kk + xc4[j]);
#pragma unroll
            for (int j = 0; j < 3; j++)
                cpa16(wdst[nb][j], wsrc[j] + (size_t)(kk + wrow[j]) * HEAD);
        }
        CPA_COMMIT();         // (empty group on c=11 keeps wait semantics exact)
        CPA_WAIT1();          // chunk c's group complete
        __syncthreads();      // cross-thread visibility of chunk c

        const float* Xb = Xs[cb];
        const float* Wb = Ws[cb];
#pragma unroll
        for (int ks = 0; ks < 4; ks++) {
            const int kb = ks * 8;
            unsigned a0[4], a1[4];
            const int rA = wm * 32 + g;
            a0[0] = f2tf(Xb[rA * XPAD + kb + t]);
            a0[1] = f2tf(Xb[(rA + 8) * XPAD + kb + t]);
            a0[2] = f2tf(Xb[rA * XPAD + kb + t + 4]);
            a0[3] = f2tf(Xb[(rA + 8) * XPAD + kb + t + 4]);
            a1[0] = f2tf(Xb[(rA + 16) * XPAD + kb + t]);
            a1[1] = f2tf(Xb[(rA + 24) * XPAD + kb + t]);
            a1[2] = f2tf(Xb[(rA + 16) * XPAD + kb + t + 4]);
            a1[3] = f2tf(Xb[(rA + 24) * XPAD + kb + t + 4]);
#pragma unroll
            for (int f = 0; f < 6; f++) {
                int col = wn * 48 + f * 8 + g;
                unsigned b0 = f2tf(Wb[(kb + t) * WPAD + col]);
                unsigned b1 = f2tf(Wb[(kb + t + 4) * WPAD + col]);
                mma_tf32(acc[f], a0, b0, b1);
                mma_tf32(acc[6 + f], a1, b0, b1);
            }
        }
        __syncthreads();      // all readers done before next iter overwrites cb
    }

    // ---- epilogue: route columns to K / Q / V ----
#pragma unroll
    for (int mf = 0; mf < 2; mf++) {
#pragma unroll
        for (int f = 0; f < 6; f++) {
            const float* a = acc[mf * 6 + f];
            int n = wn * 48 + f * 8 + 2 * t;
            float* dst;
            int nn;
            if (n < 64)       { dst = g_K; nn = n; }
            else if (n < 128) { dst = g_Q; nn = n - 64; }
            else              { dst = g_V; nn = n - 128; }
            size_t row = (size_t)(r0 + wm * 32 + mf * 16 + g);
            *(float2*)&dst[row * HEAD + nn]       = make_float2(a[0], a[1]);
            *(float2*)&dst[(row + 8) * HEAD + nn] = make_float2(a[2], a[3]);
        }
    }
}

// ---------------------------------------------------------------------------
// Kernel 2: causal attention, tf32 mma.sync, flash online softmax.
// (exact known-good R6 version: 256 thr, paired q-tiles {w, 15-w})
// ---------------------------------------------------------------------------
#define KVPAD 68
#define QPAD  68
#define PPAD  36

__global__ __launch_bounds__(256, 1)
void attn_kernel(float* __restrict__ out)
{
    extern __shared__ float smf[];
    float* Ks = smf;
    float* Vs = Ks + SEQ * KVPAD;
    float* Qs = Vs + SEQ * KVPAD;
    float* Pb = Qs + 8 * 16 * QPAD;

    const int b    = blockIdx.x;
    const int tid  = threadIdx.x;
    const int lane = tid & 31;
    const int warp = tid >> 5;
    const int g = lane >> 2;
    const int t = lane & 3;
    const size_t base = (size_t)b * SEQ * HEAD;

    for (int i = tid; i < SEQ * HEAD / 4; i += 256) {
        int s = i >> 4;
        int d = (i & 15) * 4;
        float4 k4 = *(const float4*)&g_K[base + (size_t)s * HEAD + d];
        float4 v4 = *(const float4*)&g_V[base + (size_t)s * HEAD + d];
        k4.x = f2tf_f(k4.x); k4.y = f2tf_f(k4.y);
        k4.z = f2tf_f(k4.z); k4.w = f2tf_f(k4.w);
        v4.x = f2tf_f(v4.x); v4.y = f2tf_f(v4.y);
        v4.z = f2tf_f(v4.z); v4.w = f2tf_f(v4.w);
        *(float4*)&Ks[s * KVPAD + d] = k4;
        *(float4*)&Vs[s * KVPAD + d] = v4;
    }
    __syncthreads();

    float* Qw = Qs + warp * 16 * QPAD;
    float* Pw = Pb + warp * 16 * PPAD;

#pragma unroll
    for (int pass = 0; pass < 2; pass++) {
        const int qt = pass ? (15 - warp) : warp;
        const int qr0 = qt * 16;

#pragma unroll
        for (int i = 0; i < 8; i++) {
            int idx = lane + i * 32;
            int row = idx >> 4;
            int c4  = (idx & 15) * 4;
            float4 q4 = *(const float4*)&g_Q[base + (size_t)(qr0 + row) * HEAD + c4];
            q4.x = f2tf_f(q4.x); q4.y = f2tf_f(q4.y);
            q4.z = f2tf_f(q4.z); q4.w = f2tf_f(q4.w);
            *(float4*)&Qw[row * QPAD + c4] = q4;
        }
        __syncwarp();

        unsigned qf[8][4];
#pragma unroll
        for (int ks = 0; ks < 8; ks++) {
            int kb = ks * 8;
            qf[ks][0] = __float_as_uint(Qw[g * QPAD + kb + t]);
            qf[ks][1] = __float_as_uint(Qw[(g + 8) * QPAD + kb + t]);
            qf[ks][2] = __float_as_uint(Qw[g * QPAD + kb + t + 4]);
            qf[ks][3] = __float_as_uint(Qw[(g + 8) * QPAD + kb + t + 4]);
        }

        float of[8][4];
#pragma unroll
        for (int f = 0; f < 8; f++)
#pragma unroll
            for (int j = 0; j < 4; j++) of[f][j] = 0.f;

        float m0 = -1e30f, m1 = -1e30f, l0 = 0.f, l1 = 0.f;
        const int rg  = qr0 + g;
        const int rg8 = rg + 8;
        const int jmax = (qr0 + 15) >> 5;

        for (int j = 0; j <= jmax; j++) {
            float s[4][4];
#pragma unroll
            for (int nf = 0; nf < 4; nf++)
#pragma unroll
                for (int e = 0; e < 4; e++) s[nf][e] = 0.f;

#pragma unroll
            for (int ks = 0; ks < 8; ks++) {
                int kb = ks * 8;
#pragma unroll
                for (int nf = 0; nf < 4; nf++) {
                    int col = j * 32 + nf * 8 + g;
                    unsigned b0 = __float_as_uint(Ks[col * KVPAD + kb + t]);
                    unsigned b1 = __float_as_uint(Ks[col * KVPAD + kb + t + 4]);
                    mma_tf32(s[nf], qf[ks], b0, b1);
                }
            }

#pragma unroll
            for (int nf = 0; nf < 4; nf++) {
                int c0 = j * 32 + nf * 8 + 2 * t;
                s[nf][0] *= 0.125f; s[nf][1] *= 0.125f;
                s[nf][2] *= 0.125f; s[nf][3] *= 0.125f;
                if (j == jmax) {
                    if (c0 > rg)      s[nf][0] = -1e30f;
                    if (c0 + 1 > rg)  s[nf][1] = -1e30f;
                    if (c0 > rg8)     s[nf][2] = -1e30f;
                    if (c0 + 1 > rg8) s[nf][3] = -1e30f;
                }
            }

            float nm0 = m0, nm1 = m1;
#pragma unroll
            for (int nf = 0; nf < 4; nf++) {
                nm0 = fmaxf(nm0, fmaxf(s[nf][0], s[nf][1]));
                nm1 = fmaxf(nm1, fmaxf(s[nf][2], s[nf][3]));
            }
            nm0 = fmaxf(nm0, __shfl_xor_sync(0xFFFFFFFFu, nm0, 1));
            nm0 = fmaxf(nm0, __shfl_xor_sync(0xFFFFFFFFu, nm0, 2));
            nm1 = fmaxf(nm1, __shfl_xor_sync(0xFFFFFFFFu, nm1, 1));
            nm1 = fmaxf(nm1, __shfl_xor_sync(0xFFFFFFFFu, nm1, 2));

            float al0 = __expf(m0 - nm0);
            float al1 = __expf(m1 - nm1);

            float ps0 = 0.f, ps1 = 0.f;
#pragma unroll
            for (int nf = 0; nf < 4; nf++) {
                float p0 = __expf(s[nf][0] - nm0);
                float p1 = __expf(s[nf][1] - nm0);
                float p2 = __expf(s[nf][2] - nm1);
                float p3 = __expf(s[nf][3] - nm1);
                ps0 += p0 + p1;
                ps1 += p2 + p3;
                int cl = nf * 8 + 2 * t;
                *(float2*)&Pw[g * PPAD + cl] =
                    make_float2(f2tf_f(p0), f2tf_f(p1));
                *(float2*)&Pw[(g + 8) * PPAD + cl] =
                    make_float2(f2tf_f(p2), f2tf_f(p3));
            }
            ps0 += __shfl_xor_sync(0xFFFFFFFFu, ps0, 1);
            ps0 += __shfl_xor_sync(0xFFFFFFFFu, ps0, 2);
            ps1 += __shfl_xor_sync(0xFFFFFFFFu, ps1, 1);
            ps1 += __shfl_xor_sync(0xFFFFFFFFu, ps1, 2);

            l0 = l0 * al0 + ps0;
            l1 = l1 * al1 + ps1;
            m0 = nm0; m1 = nm1;

#pragma unroll
            for (int f = 0; f < 8; f++) {
                of[f][0] *= al0; of[f][1] *= al0;
                of[f][2] *= al1; of[f][3] *= al1;
            }
            __syncwarp();

#pragma unroll
            for (int ks = 0; ks < 4; ks++) {
                int kb = ks * 8;
                unsigned pa[4];
                pa[0] = __float_as_uint(Pw[g * PPAD + kb + t]);
                pa[1] = __float_as_uint(Pw[(g + 8) * PPAD + kb + t]);
                pa[2] = __float_as_uint(Pw[g * PPAD + kb + t + 4]);
                pa[3] = __float_as_uint(Pw[(g + 8) * PPAD + kb + t + 4]);
                int vr = j * 32 + kb;
#pragma unroll
                for (int nf = 0; nf < 8; nf++) {
                    int col = nf * 8 + g;
                    unsigned b0 = __float_as_uint(Vs[(vr + t) * KVPAD + col]);
                    unsigned b1 = __float_as_uint(Vs[(vr + t + 4) * KVPAD + col]);
                    mma_tf32(of[nf], pa, b0, b1);
                }
            }
            __syncwarp();
        }

        float inv0 = 1.f / l0;
        float inv1 = 1.f / l1;
#pragma unroll
        for (int nf = 0; nf < 8; nf++) {
            int col = nf * 8 + 2 * t;
            size_t row = (size_t)(qr0 + g);
            *(float2*)&out[base + row * HEAD + col] =
                make_float2(of[nf][0] * inv0, of[nf][1] * inv0);
            *(float2*)&out[base + (row + 8) * HEAD + col] =
                make_float2(of[nf][2] * inv1, of[nf][3] * inv1);
        }
    }
}

// ---------------------------------------------------------------------------
extern "C" void kernel_launch(void* const* d_in, const int* in_sizes, int n_in,
                              void* d_out, int out_size)
{
    const float* X  = (const float*)d_in[0];
    const float* Wk = (const float*)d_in[1];
    const float* Wq = (const float*)d_in[2];
    const float* Wv = (const float*)d_in[3];
    float* out = (float*)d_out;

    const int attn_smem =
        (2 * SEQ * KVPAD + 8 * 16 * QPAD + 8 * 16 * PPAD) * (int)sizeof(float);

    static bool attr_set = false;
    if (!attr_set) {
        cudaFuncSetAttribute(proj_kernel,
                             cudaFuncAttributeMaxDynamicSharedMemorySize,
                             PROJ_SMEM);
        cudaFuncSetAttribute(attn_kernel,
                             cudaFuncAttributeMaxDynamicSharedMemorySize,
                             attn_smem);
        attr_set = true;
    }

    proj_kernel<<<(BATCH * SEQ) / 128, 512, PROJ_SMEM>>>(X, Wk, Wq, Wv);
    attn_kernel<<<BATCH, 256, attn_smem>>>(out);
}

// round 13
// speedup vs baseline: 1.4809x; 1.0728x over previous
#include <cuda_runtime.h>
#include <cuda_bf16.h>
#include <cstdint>
#include <math.h>

#define BATCH 512
#define SEQ 256
#define EMBED 384
#define HEAD 64

// Scratch for projected Q, K, V
__device__ float g_Q[BATCH * SEQ * HEAD];
__device__ float g_K[BATCH * SEQ * HEAD];
__device__ float g_V[BATCH * SEQ * HEAD];

// ---------------------------------------------------------------------------
// helpers
// ---------------------------------------------------------------------------
__device__ __forceinline__ float f2tf_f(float x) {
    unsigned r;
    asm("cvt.rna.tf32.f32 %0, %1;" : "=r"(r) : "f"(x));
    return __uint_as_float(r);
}
__device__ __forceinline__ unsigned f2tf(float x) {
    unsigned r;
    asm("cvt.rna.tf32.f32 %0, %1;" : "=r"(r) : "f"(x));
    return r;
}

__device__ __forceinline__ void mma_tf32(float* d, const unsigned* a,
                                         unsigned b0, unsigned b1) {
    asm volatile(
        "mma.sync.aligned.m16n8k8.row.col.f32.tf32.tf32.f32 "
        "{%0,%1,%2,%3}, {%4,%5,%6,%7}, {%8,%9}, {%0,%1,%2,%3};\n"
        : "+f"(d[0]), "+f"(d[1]), "+f"(d[2]), "+f"(d[3])
        : "r"(a[0]), "r"(a[1]), "r"(a[2]), "r"(a[3]), "r"(b0), "r"(b1));
}

__device__ __forceinline__ uint32_t smem_u32(const void* p) {
    uint32_t a;
    asm("{ .reg .u64 t; cvta.to.shared.u64 t, %1; cvt.u32.u64 %0, t; }"
        : "=r"(a) : "l"(p));
    return a;
}

__device__ __forceinline__ void cpa16(uint32_t dst, const void* src) {
    asm volatile("cp.async.cg.shared.global [%0], [%1], 16;"
                 :: "r"(dst), "l"(src) : "memory");
}
#define CPA_COMMIT() asm volatile("cp.async.commit_group;" ::: "memory")
#define CPA_WAIT1()  asm volatile("cp.async.wait_group 1;" ::: "memory")

// ---------------------------------------------------------------------------
// Kernel 1: fused projection GEMM, cp.async double-buffered, 512 threads.
// (byte-identical to the ~189us R9 version)
// ---------------------------------------------------------------------------
#define XPAD 36
#define WPAD 200
#define XS_FLOATS (128 * XPAD)
#define WS_FLOATS (32 * WPAD)
#define PROJ_SMEM ((2 * XS_FLOATS + 2 * WS_FLOATS) * 4)

__global__ __launch_bounds__(512, 1)
void proj_kernel(const float* __restrict__ X,
                 const float* __restrict__ Wk,
                 const float* __restrict__ Wq,
                 const float* __restrict__ Wv)
{
    extern __shared__ float sm[];
    float* Xs[2] = {sm, sm + XS_FLOATS};
    float* Ws[2] = {sm + 2 * XS_FLOATS, sm + 2 * XS_FLOATS + WS_FLOATS};

    const int tid  = threadIdx.x;
    const int lane = tid & 31;
    const int warp = tid >> 5;
    const int g = lane >> 2;
    const int t = lane & 3;
    const int wm = warp & 3;
    const int wn = warp >> 2;
    const int r0 = blockIdx.x * 128;

    int xrow[2], xc4[2];
    uint32_t xdst[2][2];
#pragma unroll
    for (int j = 0; j < 2; j++) {
        int idx = tid + j * 512;
        xrow[j] = idx >> 3;
        xc4[j]  = (idx & 7) * 4;
        xdst[0][j] = smem_u32(&Xs[0][xrow[j] * XPAD + xc4[j]]);
        xdst[1][j] = smem_u32(&Xs[1][xrow[j] * XPAD + xc4[j]]);
    }
    int wrow[3];
    const float* wsrc[3];
    uint32_t wdst[2][3];
#pragma unroll
    for (int j = 0; j < 3; j++) {
        int idx = tid + j * 512;
        wrow[j] = idx / 48;
        int c = (idx % 48) * 4;
        if (c < 64)       wsrc[j] = Wk + c;
        else if (c < 128) wsrc[j] = Wq + (c - 64);
        else              wsrc[j] = Wv + (c - 128);
        wdst[0][j] = smem_u32(&Ws[0][wrow[j] * WPAD + c]);
        wdst[1][j] = smem_u32(&Ws[1][wrow[j] * WPAD + c]);
    }

    float acc[12][4];
#pragma unroll
    for (int f = 0; f < 12; f++)
#pragma unroll
        for (int j = 0; j < 4; j++) acc[f][j] = 0.f;

#pragma unroll
    for (int j = 0; j < 2; j++)
        cpa16(xdst[0][j], X + (size_t)(r0 + xrow[j]) * EMBED + xc4[j]);
#pragma unroll
    for (int j = 0; j < 3; j++)
        cpa16(wdst[0][j], wsrc[j] + (size_t)wrow[j] * HEAD);
    CPA_COMMIT();

#pragma unroll 1
    for (int c = 0; c < 12; c++) {
        const int cb = c & 1;
        if (c < 11) {
            const int nb = 1 - cb;
            const int kk = (c + 1) * 32;
#pragma unroll
            for (int j = 0; j < 2; j++)
                cpa16(xdst[nb][j], X + (size_t)(r0 + xrow[j]) * EMBED + kk + xc4[j]);
#pragma unroll
            for (int j = 0; j < 3; j++)
                cpa16(wdst[nb][j], wsrc[j] + (size_t)(kk + wrow[j]) * HEAD);
        }
        CPA_COMMIT();
        CPA_WAIT1();
        __syncthreads();

        const float* Xb = Xs[cb];
        const float* Wb = Ws[cb];
#pragma unroll
        for (int ks = 0; ks < 4; ks++) {
            const int kb = ks * 8;
            unsigned a0[4], a1[4];
            const int rA = wm * 32 + g;
            a0[0] = f2tf(Xb[rA * XPAD + kb + t]);
            a0[1] = f2tf(Xb[(rA + 8) * XPAD + kb + t]);
            a0[2] = f2tf(Xb[rA * XPAD + kb + t + 4]);
            a0[3] = f2tf(Xb[(rA + 8) * XPAD + kb + t + 4]);
            a1[0] = f2tf(Xb[(rA + 16) * XPAD + kb + t]);
            a1[1] = f2tf(Xb[(rA + 24) * XPAD + kb + t]);
            a1[2] = f2tf(Xb[(rA + 16) * XPAD + kb + t + 4]);
            a1[3] = f2tf(Xb[(rA + 24) * XPAD + kb + t + 4]);
#pragma unroll
            for (int f = 0; f < 6; f++) {
                int col = wn * 48 + f * 8 + g;
                unsigned b0 = f2tf(Wb[(kb + t) * WPAD + col]);
                unsigned b1 = f2tf(Wb[(kb + t + 4) * WPAD + col]);
                mma_tf32(acc[f], a0, b0, b1);
                mma_tf32(acc[6 + f], a1, b0, b1);
            }
        }
        __syncthreads();
    }

#pragma unroll
    for (int mf = 0; mf < 2; mf++) {
#pragma unroll
        for (int f = 0; f < 6; f++) {
            const float* a = acc[mf * 6 + f];
            int n = wn * 48 + f * 8 + 2 * t;
            float* dst;
            int nn;
            if (n < 64)       { dst = g_K; nn = n; }
            else if (n < 128) { dst = g_Q; nn = n - 64; }
            else              { dst = g_V; nn = n - 128; }
            size_t row = (size_t)(r0 + wm * 32 + mf * 16 + g);
            *(float2*)&dst[row * HEAD + nn]       = make_float2(a[0], a[1]);
            *(float2*)&dst[(row + 8) * HEAD + nn] = make_float2(a[2], a[3]);
        }
    }
}

// ---------------------------------------------------------------------------
// Kernel 2: causal attention with KV-halved staging -> 102 KB smem -> 2 CTA/SM.
// 256 thr, 8 warps. Warp w: tile A = w (fully in KV half 0), then tile B =
// 15-w chunks 0..3 (half 0), block restage to half 1, tile B chunks 4..jmax.
// P aliases the dead Q buffer. Per-row chunk order unchanged (j ascending).
// ---------------------------------------------------------------------------
#define KVPAD 68
#define QPAD  68
#define KVROWS 128
#define ATTN_SMEM ((2 * KVROWS * KVPAD + 8 * 16 * QPAD) * (int)sizeof(float))

// one kv-chunk of flash attention for a 16-row q tile
__device__ __forceinline__ void attn_chunk(
    const float* __restrict__ Ks, const float* __restrict__ Vs,
    float* __restrict__ Pw, const unsigned qf[8][4], float of[8][4],
    float& m0, float& m1, float& l0, float& l1,
    int bj,            // chunk index within the staged buffer (0..3)
    bool mask, int rg, int rg8, int cbase,   // global col base of this chunk
    int g, int t)
{
    float s[4][4];
#pragma unroll
    for (int nf = 0; nf < 4; nf++)
#pragma unroll
        for (int e = 0; e < 4; e++) s[nf][e] = 0.f;

#pragma unroll
    for (int ks = 0; ks < 8; ks++) {
        int kb = ks * 8;
#pragma unroll
        for (int nf = 0; nf < 4; nf++) {
            int col = bj * 32 + nf * 8 + g;
            unsigned b0 = __float_as_uint(Ks[col * KVPAD + kb + t]);
            unsigned b1 = __float_as_uint(Ks[col * KVPAD + kb + t + 4]);
            mma_tf32(s[nf], qf[ks], b0, b1);
        }
    }

#pragma unroll
    for (int nf = 0; nf < 4; nf++) {
        int c0 = cbase + nf * 8 + 2 * t;
        s[nf][0] *= 0.125f; s[nf][1] *= 0.125f;
        s[nf][2] *= 0.125f; s[nf][3] *= 0.125f;
        if (mask) {
            if (c0 > rg)      s[nf][0] = -1e30f;
            if (c0 + 1 > rg)  s[nf][1] = -1e30f;
            if (c0 > rg8)     s[nf][2] = -1e30f;
            if (c0 + 1 > rg8) s[nf][3] = -1e30f;
        }
    }

    float nm0 = m0, nm1 = m1;
#pragma unroll
    for (int nf = 0; nf < 4; nf++) {
        nm0 = fmaxf(nm0, fmaxf(s[nf][0], s[nf][1]));
        nm1 = fmaxf(nm1, fmaxf(s[nf][2], s[nf][3]));
    }
    nm0 = fmaxf(nm0, __shfl_xor_sync(0xFFFFFFFFu, nm0, 1));
    nm0 = fmaxf(nm0, __shfl_xor_sync(0xFFFFFFFFu, nm0, 2));
    nm1 = fmaxf(nm1, __shfl_xor_sync(0xFFFFFFFFu, nm1, 1));
    nm1 = fmaxf(nm1, __shfl_xor_sync(0xFFFFFFFFu, nm1, 2));

    float al0 = __expf(m0 - nm0);
    float al1 = __expf(m1 - nm1);

    float ps0 = 0.f, ps1 = 0.f;
#pragma unroll
    for (int nf = 0; nf < 4; nf++) {
        float p0 = __expf(s[nf][0] - nm0);
        float p1 = __expf(s[nf][1] - nm0);
        float p2 = __expf(s[nf][2] - nm1);
        float p3 = __expf(s[nf][3] - nm1);
        ps0 += p0 + p1;
        ps1 += p2 + p3;
        int cl = nf * 8 + 2 * t;
        *(float2*)&Pw[g * QPAD + cl] =
            make_float2(f2tf_f(p0), f2tf_f(p1));
        *(float2*)&Pw[(g + 8) * QPAD + cl] =
            make_float2(f2tf_f(p2), f2tf_f(p3));
    }
    ps0 += __shfl_xor_sync(0xFFFFFFFFu, ps0, 1);
    ps0 += __shfl_xor_sync(0xFFFFFFFFu, ps0, 2);
    ps1 += __shfl_xor_sync(0xFFFFFFFFu, ps1, 1);
    ps1 += __shfl_xor_sync(0xFFFFFFFFu, ps1, 2);

    l0 = l0 * al0 + ps0;
    l1 = l1 * al1 + ps1;
    m0 = nm0; m1 = nm1;

#pragma unroll
    for (int f = 0; f < 8; f++) {
        of[f][0] *= al0; of[f][1] *= al0;
        of[f][2] *= al1; of[f][3] *= al1;
    }
    __syncwarp();

#pragma unroll
    for (int ks = 0; ks < 4; ks++) {
        int kb = ks * 8;
        unsigned pa[4];
        pa[0] = __float_as_uint(Pw[g * QPAD + kb + t]);
        pa[1] = __float_as_uint(Pw[(g + 8) * QPAD + kb + t]);
        pa[2] = __float_as_uint(Pw[g * QPAD + kb + t + 4]);
        pa[3] = __float_as_uint(Pw[(g + 8) * QPAD + kb + t + 4]);
        int vr = bj * 32 + kb;
#pragma unroll
        for (int nf = 0; nf < 8; nf++) {
            int col = nf * 8 + g;
            unsigned b0 = __float_as_uint(Vs[(vr + t) * KVPAD + col]);
            unsigned b1 = __float_as_uint(Vs[(vr + t + 4) * KVPAD + col]);
            mma_tf32(of[nf], pa, b0, b1);
        }
    }
    __syncwarp();
}

__global__ __launch_bounds__(256, 2)
void attn_kernel(float* __restrict__ out)
{
    extern __shared__ float smf[];
    float* Ks = smf;                        // [128][68]
    float* Vs = Ks + KVROWS * KVPAD;        // [128][68]
    float* QP = Vs + KVROWS * KVPAD;        // [8][16][68]

    const int b    = blockIdx.x;
    const int tid  = threadIdx.x;
    const int lane = tid & 31;
    const int warp = tid >> 5;
    const int g = lane >> 2;
    const int t = lane & 3;
    const size_t base = (size_t)b * SEQ * HEAD;

    // ---- stage KV half 0 (rows 0..127), tf32-rounded ----
    for (int i = tid; i < KVROWS * HEAD / 4; i += 256) {
        int s = i >> 4;
        int d = (i & 15) * 4;
        float4 k4 = *(const float4*)&g_K[base + (size_t)s * HEAD + d];
        float4 v4 = *(const float4*)&g_V[base + (size_t)s * HEAD + d];
        k4.x = f2tf_f(k4.x); k4.y = f2tf_f(k4.y);
        k4.z = f2tf_f(k4.z); k4.w = f2tf_f(k4.w);
        v4.x = f2tf_f(v4.x); v4.y = f2tf_f(v4.y);
        v4.z = f2tf_f(v4.z); v4.w = f2tf_f(v4.w);
        *(float4*)&Ks[s * KVPAD + d] = k4;
        *(float4*)&Vs[s * KVPAD + d] = v4;
    }
    __syncthreads();

    float* Qw = QP + warp * 16 * QPAD;
    unsigned qf[8][4];
    float of[8][4];
    float m0, m1, l0, l1;

    // ================= tile A = warp (rows warp*16..+15, all kv in half 0) ==
    {
        const int qr0 = warp * 16;
#pragma unroll
        for (int i = 0; i < 8; i++) {
            int idx = lane + i * 32;
            int row = idx >> 4;
            int c4  = (idx & 15) * 4;
            float4 q4 = *(const float4*)&g_Q[base + (size_t)(qr0 + row) * HEAD + c4];
            q4.x = f2tf_f(q4.x); q4.y = f2tf_f(q4.y);
            q4.z = f2tf_f(q4.z); q4.w = f2tf_f(q4.w);
            *(float4*)&Qw[row * QPAD + c4] = q4;
        }
        __syncwarp();
#pragma unroll
        for (int ks = 0; ks < 8; ks++) {
            int kb = ks * 8;
            qf[ks][0] = __float_as_uint(Qw[g * QPAD + kb + t]);
            qf[ks][1] = __float_as_uint(Qw[(g + 8) * QPAD + kb + t]);
            qf[ks][2] = __float_as_uint(Qw[g * QPAD + kb + t + 4]);
            qf[ks][3] = __float_as_uint(Qw[(g + 8) * QPAD + kb + t + 4]);
        }
        __syncwarp();

#pragma unroll
        for (int f = 0; f < 8; f++)
#pragma unroll
            for (int j = 0; j < 4; j++) of[f][j] = 0.f;
        m0 = -1e30f; m1 = -1e30f; l0 = 0.f; l1 = 0.f;
        const int rg = qr0 + g, rg8 = rg + 8;
        const int jmax = (qr0 + 15) >> 5;

        for (int j = 0; j <= jmax; j++)
            attn_chunk(Ks, Vs, Qw, qf, of, m0, m1, l0, l1,
                       j, j == jmax, rg, rg8, j * 32, g, t);

        float inv0 = 1.f / l0, inv1 = 1.f / l1;
#pragma unroll
        for (int nf = 0; nf < 8; nf++) {
            int col = nf * 8 + 2 * t;
            size_t row = (size_t)(qr0 + g);
            *(float2*)&out[base + row * HEAD + col] =
                make_float2(of[nf][0] * inv0, of[nf][1] * inv0);
            *(float2*)&out[base + (row + 8) * HEAD + col] =
                make_float2(of[nf][2] * inv1, of[nf][3] * inv1);
        }
        __syncwarp();
    }

    // ================= tile B = 15-warp: chunks 0..3 vs half 0 ============
    const int qr0b = (15 - warp) * 16;
    {
#pragma unroll
        for (int i = 0; i < 8; i++) {
            int idx = lane + i * 32;
            int row = idx >> 4;
            int c4  = (idx & 15) * 4;
            float4 q4 = *(const float4*)&g_Q[base + (size_t)(qr0b + row) * HEAD + c4];
            q4.x = f2tf_f(q4.x); q4.y = f2tf_f(q4.y);
            q4.z = f2tf_f(q4.z); q4.w = f2tf_f(q4.w);
            *(float4*)&Qw[row * QPAD + c4] = q4;
        }
        __syncwarp();
#pragma unroll
        for (int ks = 0; ks < 8; ks++) {
            int kb = ks * 8;
            qf[ks][0] = __float_as_uint(Qw[g * QPAD + kb + t]);
            qf[ks][1] = __float_as_uint(Qw[(g + 8) * QPAD + kb + t]);
            qf[ks][2] = __float_as_uint(Qw[g * QPAD + kb + t + 4]);
            qf[ks][3] = __float_as_uint(Qw[(g + 8) * QPAD + kb + t + 4]);
        }
        __syncwarp();

#pragma unroll
        for (int f = 0; f < 8; f++)
#pragma unroll
            for (int j = 0; j < 4; j++) of[f][j] = 0.f;
        m0 = -1e30f; m1 = -1e30f; l0 = 0.f; l1 = 0.f;
        const int rg = qr0b + g, rg8 = rg + 8;

        // chunks 0..3 are fully unmasked for rows >= 128
        for (int j = 0; j < 4; j++)
            attn_chunk(Ks, Vs, Qw, qf, of, m0, m1, l0, l1,
                       j, false, rg, rg8, j * 32, g, t);
    }

    // ---- restage KV half 1 (rows 128..255) ----
    __syncthreads();
    for (int i = tid; i < KVROWS * HEAD / 4; i += 256) {
        int s = i >> 4;
        int d = (i & 15) * 4;
        float4 k4 = *(const float4*)&g_K[base + (size_t)(s + 128) * HEAD + d];
        float4 v4 = *(const float4*)&g_V[base + (size_t)(s + 128) * HEAD + d];
        k4.x = f2tf_f(k4.x); k4.y = f2tf_f(k4.y);
        k4.z = f2tf_f(k4.z); k4.w = f2tf_f(k4.w);
        v4.x = f2tf_f(v4.x); v4.y = f2tf_f(v4.y);
        v4.z = f2tf_f(v4.z); v4.w = f2tf_f(v4.w);
        *(float4*)&Ks[s * KVPAD + d] = k4;
        *(float4*)&Vs[s * KVPAD + d] = v4;
    }
    __syncthreads();

    // ================= tile B continued: chunks 4..jmaxB vs half 1 ========
    {
        const int rg = qr0b + g, rg8 = rg + 8;
        const int jmax = (qr0b + 15) >> 5;    // 4..7
        for (int j = 4; j <= jmax; j++)
            attn_chunk(Ks, Vs, Qw, qf, of, m0, m1, l0, l1,
                       j - 4, j == jmax, rg, rg8, j * 32, g, t);

        float inv0 = 1.f / l0, inv1 = 1.f / l1;
#pragma unroll
        for (int nf = 0; nf < 8; nf++) {
            int col = nf * 8 + 2 * t;
            size_t row = (size_t)(qr0b + g);
            *(float2*)&out[base + row * HEAD + col] =
                make_float2(of[nf][0] * inv0, of[nf][1] * inv0);
            *(float2*)&out[base + (row + 8) * HEAD + col] =
                make_float2(of[nf][2] * inv1, of[nf][3] * inv1);
        }
    }
}

// ---------------------------------------------------------------------------
extern "C" void kernel_launch(void* const* d_in, const int* in_sizes, int n_in,
                              void* d_out, int out_size)
{
    const float* X  = (const float*)d_in[0];
    const float* Wk = (const float*)d_in[1];
    const float* Wq = (const float*)d_in[2];
    const float* Wv = (const float*)d_in[3];
    float* out = (float*)d_out;

    static bool attr_set = false;
    if (!attr_set) {
        cudaFuncSetAttribute(proj_kernel,
                             cudaFuncAttributeMaxDynamicSharedMemorySize,
                             PROJ_SMEM);
        cudaFuncSetAttribute(attn_kernel,
                             cudaFuncAttributeMaxDynamicSharedMemorySize,
                             ATTN_SMEM);
        attr_set = true;
    }

    proj_kernel<<<(BATCH * SEQ) / 128, 512, PROJ_SMEM>>>(X, Wk, Wq, Wv);
    attn_kernel<<<BATCH, 256, ATTN_SMEM>>>(out);
}